// round 14
// baseline (speedup 1.0000x reference)
#include <cuda_runtime.h>
#include <math.h>

// Problem constants
#define BN   8192
#define DN   64
#define CTXN 256
#define HN   512
#define ROWS 32        // rows per CTA
#define NTHR 256
#define CTXP 36        // padded row-stride for staged context (16B-aligned)
#define PRIV 2052      // per-warp private a1 stride in floats (512*4 + 4 pad)

typedef unsigned long long u64;

// ---------------- static device scratch (no allocations allowed) -------------
__device__ __align__(16) float g_W2r[HN * HN];    // [k_in][n_out], permuted+masked
__device__ __align__(16) float g_W1r[DN * HN];    // [input d][p], permuted+masked
__device__ __align__(16) float g_WomMu[DN * HN];  // [step i][p]
__device__ __align__(16) float g_WomSc[DN * HN];  // [step i][p]
__device__ __align__(16) float g_Wcr[CTXN * HN];  // [c][p] permuted Wc
__device__ __align__(16) float g_b1r[HN];
__device__ __align__(16) float g_b2r[HN];

// ------------- degree-sorted permutation (analytic) --------------------------
// mh[h] = h % 63 + 1 ; degrees 1..8 appear 9x, 9..63 appear 8x.
__device__ __forceinline__ int degp(int p) { return (p < 72) ? (p / 9 + 1) : (p / 8); }
__device__ __forceinline__ int origp(int p) {
    int d, j;
    if (p < 72) { d = p / 9 + 1; j = p - 9 * (d - 1); }
    else        { d = p / 8;     j = p - 8 * d; }
    return (d - 1) + 63 * j;
}
__device__ __forceinline__ int cntd(int d) {
    return (d <= 0) ? 0 : ((d <= 8) ? 9 * d : 8 * d + 8);
}

// ------------- packed f32x2 helpers ------------------------------------------
__device__ __forceinline__ u64 dup2(float a) {
    u64 r; asm("mov.b64 %0, {%1, %1};" : "=l"(r) : "f"(a)); return r;
}
__device__ __forceinline__ u64 pk2(float a, float b) {
    u64 r; asm("mov.b64 %0, {%1, %2};" : "=l"(r) : "f"(a), "f"(b)); return r;
}
__device__ __forceinline__ void fma2(u64& d, u64 a, u64 b) {
    asm("fma.rn.f32x2 %0, %1, %2, %0;" : "+l"(d) : "l"(a), "l"(b));
}
__device__ __forceinline__ void unpk(u64 v, float& a, float& b) {
    asm("mov.b64 {%0, %1}, %2;" : "=f"(a), "=f"(b) : "l"(v));
}

// ------------- weight preparation (masked, permuted) --------------------------
__global__ void prep_kernel(const float* __restrict__ W1, const float* __restrict__ b1,
                            const float* __restrict__ Wc, const float* __restrict__ W2,
                            const float* __restrict__ b2, const float* __restrict__ Wo) {
    int idx = blockIdx.x * blockDim.x + threadIdx.x;
    if (idx < HN * HN) {
        int k = idx / HN, n = idx % HN;
        int dn = degp(n), dk = degp(k);
        g_W2r[idx] = (dn >= dk) ? W2[origp(n) * HN + origp(k)] : 0.f;
    }
    if (idx < DN * HN) {
        int i = idx / HN, p = idx % HN;
        int dp = degp(p), op = origp(p);
        g_W1r[idx]   = (dp >= i + 1) ? W1[op * DN + i] : 0.f;
        bool m = (dp <= i);
        g_WomMu[idx] = m ? Wo[i * HN + op] : 0.f;
        g_WomSc[idx] = m ? Wo[(DN + i) * HN + op] : 0.f;
    }
    if (idx < CTXN * HN) {
        int c = idx / HN, p = idx % HN;
        g_Wcr[idx] = Wc[origp(p) * CTXN + c];
    }
    if (idx < HN) {
        int op = origp(idx);
        g_b1r[idx] = b1[op];
        g_b2r[idx] = b2[op];
    }
}

// one k-row of weights for this lane's 16 units (interleaved: j*128 + lane*4)
struct W16 { ulonglong2 q0, q1, q2, q3; };
__device__ __forceinline__ void loadW16(W16& g, const float* p) {
    g.q0 = *(const ulonglong2*)(p);
    g.q1 = *(const ulonglong2*)(p + 128);
    g.q2 = *(const ulonglong2*)(p + 256);
    g.q3 = *(const ulonglong2*)(p + 384);
}

// ------------- main persistent kernel ----------------------------------------
// Warp-autonomous incremental MADE. Warp w owns batch rows [4w, 4w+4) and ALL
// 512 units for them. Lane owns 16 units (4 float4 chunks at j*128+lane*4) x
// 4 rows. S[n][r] accumulates b2 + sum_{k frozen} relu(a1[k]) * W2r[k][n];
// each of 512 k-rows is processed exactly once across the 64 steps. Phase 2
// has NO __syncthreads: reduction is an in-warp shfl butterfly, a1 slice is
// warp-private, outputs stored directly to gmem.
__global__ void __launch_bounds__(NTHR, 2)
made_kernel(const float* __restrict__ ctx, const float* __restrict__ eps,
            const float* __restrict__ bo, float* __restrict__ out) {
    extern __shared__ float smem[];
    const int t    = threadIdx.x;
    const int wid  = t >> 5;
    const int lane = t & 31;
    const int row0 = blockIdx.x * ROWS;
    float* a1w = smem + wid * PRIV;        // this warp's private a1 [512][4]

    // ---- Phase 0: stage context transposed (stride CTXP) ----
    for (int idx = t; idx < CTXN * ROWS; idx += NTHR) {
        int r = idx >> 8;
        int c = idx & 255;
        smem[c * CTXP + r] = ctx[(row0 + r) * CTXN + c];
    }
    __syncthreads();

    // ---- Phase 1: ctx GEMM (old layout: warp = 64 units x 32 rows) ----
    {
        const int rg  = lane >> 3;
        const int ull = lane & 7;
        const int nb1 = wid * 64 + ull * 8;
        const int r0t = rg * 8;
        u64 acc1[4][8];
#pragma unroll
        for (int a = 0; a < 4; a++)
#pragma unroll
            for (int b = 0; b < 8; b++) acc1[a][b] = 0ull;
        const float* wp = g_Wcr + nb1;
        const float* hp = smem + r0t;
#pragma unroll 2
        for (int c = 0; c < CTXN; c++) {
            ulonglong2 wA = *(const ulonglong2*)(wp);
            ulonglong2 wB = *(const ulonglong2*)(wp + 4);
            wp += HN;
            float4 v0 = *(const float4*)(hp);
            float4 v1 = *(const float4*)(hp + 4);
            hp += CTXP;
            u64 h[8];
            h[0] = dup2(v0.x); h[1] = dup2(v0.y); h[2] = dup2(v0.z); h[3] = dup2(v0.w);
            h[4] = dup2(v1.x); h[5] = dup2(v1.y); h[6] = dup2(v1.z); h[7] = dup2(v1.w);
#pragma unroll
            for (int r = 0; r < 8; r++) {
                fma2(acc1[0][r], wA.x, h[r]);
                fma2(acc1[1][r], wA.y, h[r]);
                fma2(acc1[2][r], wB.x, h[r]);
                fma2(acc1[3][r], wB.y, h[r]);
            }
        }
        __syncthreads();   // everyone done reading staged ctx
        // scatter (+b1) into per-warp private a1 arrays
#pragma unroll
        for (int up = 0; up < 4; up++) {
            int n0 = nb1 + 2 * up;
            float bA = g_b1r[n0], bB = g_b1r[n0 + 1];
#pragma unroll
            for (int rr = 0; rr < 8; rr++) {
                float lo, hi; unpk(acc1[up][rr], lo, hi);
                int r = r0t + rr;
                float* dst = smem + (r >> 2) * PRIV + (r & 3);
                dst[n0 * 4]       = lo + bA;
                dst[(n0 + 1) * 4] = hi + bB;
            }
        }
    }
    __syncthreads();   // a1 arrays complete; phase 2 is barrier-free

    // ---- Phase 2: D sequential steps, warp-autonomous ----
    // S[2j+c2][r]: unit pair (j*128 + lane*4 + 2*c2, +1), row r. Init = b2.
    u64 S[8][4];
#pragma unroll
    for (int j = 0; j < 4; j++) {
        float4 b2v = *(const float4*)(g_b2r + j * 128 + lane * 4);
#pragma unroll
        for (int r = 0; r < 4; r++) {
            S[2 * j][r]     = pk2(b2v.x, b2v.y);
            S[2 * j + 1][r] = pk2(b2v.z, b2v.w);
        }
    }

    const float* wlane = g_W2r + lane * 4;   // + k*HN + j*128
    W16 pf;
    loadW16(pf, wlane);                       // prefetch k = 0

    int kprev = 0;
    for (int i = 0; i < DN; i++) {
        const int ncur = cntd(i);

        // -- S update with newly frozen rows [kprev, ncur) --
#pragma unroll 1
        for (int k = kprev; k < ncur; k++) {
            W16 cw = pf;                              // rename, no MOVs
            int kn = (k + 1 < HN) ? (k + 1) : (HN - 1);
            loadW16(pf, wlane + kn * HN);             // prefetch next row
            float4 av = *(const float4*)(a1w + k * 4);   // relu'd, broadcast
            u64 h0 = dup2(av.x), h1 = dup2(av.y), h2 = dup2(av.z), h3 = dup2(av.w);
            fma2(S[0][0], cw.q0.x, h0); fma2(S[0][1], cw.q0.x, h1); fma2(S[0][2], cw.q0.x, h2); fma2(S[0][3], cw.q0.x, h3);
            fma2(S[1][0], cw.q0.y, h0); fma2(S[1][1], cw.q0.y, h1); fma2(S[1][2], cw.q0.y, h2); fma2(S[1][3], cw.q0.y, h3);
            fma2(S[2][0], cw.q1.x, h0); fma2(S[2][1], cw.q1.x, h1); fma2(S[2][2], cw.q1.x, h2); fma2(S[2][3], cw.q1.x, h3);
            fma2(S[3][0], cw.q1.y, h0); fma2(S[3][1], cw.q1.y, h1); fma2(S[3][2], cw.q1.y, h2); fma2(S[3][3], cw.q1.y, h3);
            fma2(S[4][0], cw.q2.x, h0); fma2(S[4][1], cw.q2.x, h1); fma2(S[4][2], cw.q2.x, h2); fma2(S[4][3], cw.q2.x, h3);
            fma2(S[5][0], cw.q2.y, h0); fma2(S[5][1], cw.q2.y, h1); fma2(S[5][2], cw.q2.y, h2); fma2(S[5][3], cw.q2.y, h3);
            fma2(S[6][0], cw.q3.x, h0); fma2(S[6][1], cw.q3.x, h1); fma2(S[6][2], cw.q3.x, h2); fma2(S[6][3], cw.q3.x, h3);
            fma2(S[7][0], cw.q3.y, h0); fma2(S[7][1], cw.q3.y, h1); fma2(S[7][2], cw.q3.y, h2); fma2(S[7][3], cw.q3.y, h3);
        }
        kprev = ncur;

        // -- epilogue: relu(S) dot Wom mu/sc (masked weights gate activity) --
        float mu[4] = {0.f, 0.f, 0.f, 0.f};
        float sc[4] = {0.f, 0.f, 0.f, 0.f};
        {
            const float* wmb = g_WomMu + i * HN + lane * 4;
            const float* wsb = g_WomSc + i * HN + lane * 4;
#pragma unroll
            for (int j = 0; j < 4; j++) {
                float4 wmv = *(const float4*)(wmb + j * 128);
                float4 wsv = *(const float4*)(wsb + j * 128);
#pragma unroll
                for (int r = 0; r < 4; r++) {
                    float s0, s1, s2, s3;
                    unpk(S[2 * j][r], s0, s1);
                    unpk(S[2 * j + 1][r], s2, s3);
                    s0 = fmaxf(s0, 0.f); s1 = fmaxf(s1, 0.f);
                    s2 = fmaxf(s2, 0.f); s3 = fmaxf(s3, 0.f);
                    mu[r] += s0 * wmv.x + s1 * wmv.y + s2 * wmv.z + s3 * wmv.w;
                    sc[r] += s0 * wsv.x + s1 * wsv.y + s2 * wsv.z + s3 * wsv.w;
                }
            }
        }
        // in-warp butterfly: all lanes end with full sums
#pragma unroll
        for (int off = 16; off > 0; off >>= 1) {
#pragma unroll
            for (int r = 0; r < 4; r++) {
                mu[r] += __shfl_xor_sync(0xffffffffu, mu[r], off);
                sc[r] += __shfl_xor_sync(0xffffffffu, sc[r], off);
            }
        }

        // -- z per row (redundant across lanes), direct gmem store --
        float z[4];
        const float boi = bo[i], bos = bo[DN + i];
#pragma unroll
        for (int r = 0; r < 4; r++) {
            float m  = mu[r] + boi;
            float ps = sc[r] + bos;
            float scl = fmaxf(ps, 0.f) + log1pf(expf(-fabsf(ps)));   // stable softplus
            int   grow = row0 + wid * 4 + r;
            float ev = __ldg(eps + grow * DN + i);
            float zz = m + scl * ev;
            z[r] = zz;
            if (lane == r) {
                int g = grow * DN + i;
                out[g]               = zz;
                out[BN * DN + g]     = m;
                out[2 * BN * DN + g] = scl;
            }
        }

        // -- rank-1 a1 update on suffix [ncur, HN); freeze-relu [ncur, nfreeze) --
        if (i < DN - 1) {
            const int nfreeze = cntd(i + 1);
            const float* w1 = g_W1r + i * HN;
            for (int p = ncur + lane; p < HN; p += 32) {
                float w = w1[p];
                float4 a = *(float4*)(a1w + p * 4);
                a.x = fmaf(z[0], w, a.x);
                a.y = fmaf(z[1], w, a.y);
                a.z = fmaf(z[2], w, a.z);
                a.w = fmaf(z[3], w, a.w);
                if (p < nfreeze) {          // freezes now: apply relu permanently
                    a.x = fmaxf(a.x, 0.f);
                    a.y = fmaxf(a.y, 0.f);
                    a.z = fmaxf(a.z, 0.f);
                    a.w = fmaxf(a.w, 0.f);
                }
                *(float4*)(a1w + p * 4) = a;
            }
        }
        __syncwarp();   // converge; order rank-1 STS before next step's LDS
    }
}

// ------------- launch ---------------------------------------------------------
extern "C" void kernel_launch(void* const* d_in, const int* in_sizes, int n_in,
                              void* d_out, int out_size) {
    (void)in_sizes; (void)n_in; (void)out_size;
    const float* ctx = (const float*)d_in[0];
    const float* eps = (const float*)d_in[1];
    const float* W1  = (const float*)d_in[2];
    const float* b1  = (const float*)d_in[3];
    const float* Wc  = (const float*)d_in[4];
    const float* W2  = (const float*)d_in[5];
    const float* b2  = (const float*)d_in[6];
    const float* Wo  = (const float*)d_in[7];
    const float* bo  = (const float*)d_in[8];
    float* out = (float*)d_out;

    prep_kernel<<<(HN * HN + 255) / 256, 256>>>(W1, b1, Wc, W2, b2, Wo);

    // smem: 8 warps x PRIV floats (covers ctx staging 256*36=9216 too)
    const int smem_bytes = 8 * PRIV * (int)sizeof(float);   // 65664 B
    cudaFuncSetAttribute(made_kernel, cudaFuncAttributeMaxDynamicSharedMemorySize, smem_bytes);
    made_kernel<<<BN / ROWS, NTHR, smem_bytes>>>(ctx, eps, bo, out);
}